// round 14
// baseline (speedup 1.0000x reference)
#include <cuda_runtime.h>
#include <cuda_fp16.h>
#include <cstdint>

#define HID       128
#define KTYPES    8
#define CH        768        // edges per main-kernel block
#define NTHREADS  256
#define GROUP     32         // edges per MMA group
#define MST       136        // smem stride (halves) for M tile  (128 + 8 pad)
#define WST       136        // smem stride (halves) for W tile
#define EPB       1024       // edges per bin block -> 313 blocks (full chip)
#define EMAX      327680

// dynamic smem (main kernel): M_s 34816 + W_s(4 buf) 34816 = 69632
#define SMEM_M_OFF   0
#define SMEM_W_OFF   (128*MST*2)
#define SMEM_BYTES   (SMEM_W_OFF + 4*GROUP*WST*2)

// ---- global scratch (static device arrays are allowed) ----
__device__ int g_cnt[KTYPES];
__device__ int g_region[KTYPES][EMAX];   // per-type edge-id lists

__device__ __forceinline__ uint32_t smem_u32(const void* p) {
    return (uint32_t)__cvta_generic_to_shared(p);
}

__device__ __forceinline__ int decode_type(const float* __restrict__ ef, int e) {
    const float4* fp = (const float4*)(ef + (size_t)e * KTYPES);
    float4 f0 = fp[0], f1 = fp[1];
    int t = 0;
    if (f0.y > 0.5f) t = 1;
    if (f0.z > 0.5f) t = 2;
    if (f0.w > 0.5f) t = 3;
    if (f1.x > 0.5f) t = 4;
    if (f1.y > 0.5f) t = 5;
    if (f1.z > 0.5f) t = 6;
    if (f1.w > 0.5f) t = 7;
    return t;
}

// ---- K1: fused decode + block-aggregated append into per-type regions ----
extern "C" __global__ void __launch_bounds__(256)
bin_kernel(const float* __restrict__ ef, int E) {
    __shared__ int h[KTYPES];
    __shared__ int cur[KTYPES];
    const int tid  = threadIdx.x;
    const int base = blockIdx.x * EPB;
    if (tid < KTYPES) h[tid] = 0;
    __syncthreads();

    int ty[EPB / 256];
#pragma unroll
    for (int i = 0; i < EPB / 256; i++) {
        const int e = base + tid + i * 256;
        int t = 0;
        if (e < E) {
            t = decode_type(ef, e);
            atomicAdd(&h[t], 1);
        }
        ty[i] = t;
    }
    __syncthreads();
    if (tid < KTYPES) cur[tid] = atomicAdd(&g_cnt[tid], h[tid]);  // reserve slice
    __syncthreads();
#pragma unroll
    for (int i = 0; i < EPB / 256; i++) {
        const int e = base + tid + i * 256;
        if (e < E) {
            const int t = ty[i];
            const int p = atomicAdd(&cur[t], 1);
            g_region[t][p] = e;
        }
    }
}

__device__ __forceinline__ uint32_t f2h(float a, float b) {
    half2 h = __floats2half2_rn(a, b);
    return *reinterpret_cast<uint32_t*>(&h);
}

// ---- K2: main GEMM over virtually-sorted spans ----
extern "C" __global__ void __launch_bounds__(NTHREADS, 3)
matmsg_main(const float* __restrict__ hw,
            const float* __restrict__ em,
            float* __restrict__ out, int E)
{
    extern __shared__ char smem[];
    half* M_s = (half*)(smem + SMEM_M_OFF);   // [128][MST]
    half* W_s = (half*)(smem + SMEM_W_OFF);   // [4][32][WST]
    __shared__ int toff[KTYPES + 1];

    const int tid = threadIdx.x;
    if (tid == 0) {
        int acc = 0;
#pragma unroll
        for (int i = 0; i < KTYPES; i++) { toff[i] = acc; acc += g_cnt[i]; }
        toff[KTYPES] = acc;
    }
    __syncthreads();

    const int base = blockIdx.x * CH;
    const int hiB  = min(base + CH, E);

    const int warp = tid >> 5;
    const int lane = tid & 31;
    const int gr_r = tid >> 3;   // row this thread gathers (0..31)
    const int gr_q = tid & 7;    // 16-float chunk of the row
    const int cq    = lane & 3;
    const int chunk = ((cq & 1) << 1) | (cq >> 1);   // lane-quad -> 4-float chunk

    float4 pf[4];                // register staging for one row-chunk

    for (int k = 0; k < KTYPES; k++) {
        const int lo = max(base, toff[k]);
        const int hi = min(hiB, toff[k + 1]);
        if (lo >= hi) continue;
        const int nk = hi - lo;
        const int* __restrict__ ridx = &g_region[k][lo - toff[k]];

        __syncthreads();  // previous type's reads of M_s/W_s done

        // stage M_k (128x128 fp32) -> fp16 smem, STS.128 chunks
        {
            const float4* mp = (const float4*)(em + (size_t)k * HID * HID);
#pragma unroll
            for (int i = 0; i < 4; i++) {
                const int pi  = tid + i * NTHREADS;   // 16-half chunk id
                const int row = pi >> 3;
                const int chk = pi & 7;
                const float4* s = mp + row * 32 + chk * 4;
                float4 v0 = s[0], v1 = s[1], v2 = s[2], v3 = s[3];
                uint4 u0, u1;
                u0.x = f2h(v0.x, v0.y); u0.y = f2h(v0.z, v0.w);
                u0.z = f2h(v1.x, v1.y); u0.w = f2h(v1.z, v1.w);
                u1.x = f2h(v2.x, v2.y); u1.y = f2h(v2.z, v2.w);
                u1.z = f2h(v3.x, v3.y); u1.w = f2h(v3.z, v3.w);
                uint4* dst = (uint4*)&M_s[row * MST + chk * 16];
                dst[0] = u0; dst[1] = u1;
            }
        }

        const int ngr = (nk + GROUP - 1) / GROUP;

        // helper lambdas (inlined): gather group g into ring buffer g&3
        auto gather_to = [&](int g) {
            const int gr = g * GROUP + gr_r;
            uint4* dst = (uint4*)&W_s[(g & 3) * GROUP * WST + gr_r * WST + gr_q * 16];
            if (gr < nk) {
                const int eg = __ldg(&ridx[gr]);
                const float4* wp = (const float4*)(hw + (size_t)eg * HID) + gr_q * 4;
#pragma unroll
                for (int j = 0; j < 4; j++) pf[j] = wp[j];
                uint4 u0, u1;
                u0.x = f2h(pf[0].x, pf[0].y); u0.y = f2h(pf[0].z, pf[0].w);
                u0.z = f2h(pf[1].x, pf[1].y); u0.w = f2h(pf[1].z, pf[1].w);
                u1.x = f2h(pf[2].x, pf[2].y); u1.y = f2h(pf[2].z, pf[2].w);
                u1.z = f2h(pf[3].x, pf[3].y); u1.w = f2h(pf[3].z, pf[3].w);
                dst[0] = u0; dst[1] = u1;
            } else {
                const uint4 z = make_uint4(0, 0, 0, 0);
                dst[0] = z; dst[1] = z;
            }
        };
        auto ldg_group = [&](int g) {
            const int gr = g * GROUP + gr_r;
            if (gr < nk) {
                const int eg = __ldg(&ridx[gr]);
                const float4* wp = (const float4*)(hw + (size_t)eg * HID) + gr_q * 4;
#pragma unroll
                for (int j = 0; j < 4; j++) pf[j] = wp[j];
            }
        };
        auto sts_group = [&](int g) {
            const int gr = g * GROUP + gr_r;
            uint4* dst = (uint4*)&W_s[(g & 3) * GROUP * WST + gr_r * WST + gr_q * 16];
            if (gr < nk) {
                uint4 u0, u1;
                u0.x = f2h(pf[0].x, pf[0].y); u0.y = f2h(pf[0].z, pf[0].w);
                u0.z = f2h(pf[1].x, pf[1].y); u0.w = f2h(pf[1].z, pf[1].w);
                u1.x = f2h(pf[2].x, pf[2].y); u1.y = f2h(pf[2].z, pf[2].w);
                u1.z = f2h(pf[3].x, pf[3].y); u1.w = f2h(pf[3].z, pf[3].w);
                dst[0] = u0; dst[1] = u1;
            } else {
                const uint4 z = make_uint4(0, 0, 0, 0);
                dst[0] = z; dst[1] = z;
            }
        };

        // hoist M_k fragments (constant for the whole span).
        // Needs M_s ready: staged above by THIS warp's stores only after the
        // block-wide barrier below — so stage W bufs 0/1 first, then sync, then hoist.
        gather_to(0);
        if (ngr > 1) gather_to(1);
        __syncthreads();  // M_s + W0/W1 ready

        uint32_t bfr[8][2][2];
#pragma unroll
        for (int ks = 0; ks < 8; ks++) {
#pragma unroll
            for (int ht = 0; ht < 2; ht++) {
                const int nrow = warp * 16 + ht * 8 + (lane & 7);
                const int kcol = ks * 16 + ((lane >> 3) & 1) * 8;
                uint32_t addr = smem_u32(&M_s[nrow * MST + kcol]);
                asm volatile("ldmatrix.sync.aligned.m8n8.x2.shared.b16 {%0,%1}, [%2];"
                             : "=r"(bfr[ks][ht][0]), "=r"(bfr[ks][ht][1]) : "r"(addr));
            }
        }

        // one group's MMA + epilogue (reads W[(g)&3], writes out)
        auto do_group = [&](int g) {
            const half* Wb = &W_s[(g & 3) * GROUP * WST];

            int eg_r[2][2];
#pragma unroll
            for (int et = 0; et < 2; et++)
#pragma unroll
                for (int hf = 0; hf < 2; hf++) {
                    const int gr = g * GROUP + et * 16 + hf * 8 + (lane >> 2);
                    eg_r[et][hf] = (gr < nk) ? __ldg(&ridx[gr]) : -1;
                }

            float c[2][2][4];
#pragma unroll
            for (int et = 0; et < 2; et++)
#pragma unroll
                for (int ht = 0; ht < 2; ht++)
#pragma unroll
                    for (int j = 0; j < 4; j++) c[et][ht][j] = 0.f;

#pragma unroll
            for (int ks = 0; ks < 8; ks++) {
#pragma unroll
                for (int et = 0; et < 2; et++) {
                    const int arow = et * 16 + (lane & 15);
                    const int acol = ks * 16 + (lane >> 4) * 8;
                    uint32_t addr = smem_u32(&Wb[arow * WST + acol]);
                    uint32_t a0, a1, a2, a3;
                    asm volatile("ldmatrix.sync.aligned.m8n8.x4.shared.b16 {%0,%1,%2,%3}, [%4];"
                                 : "=r"(a0), "=r"(a1), "=r"(a2), "=r"(a3) : "r"(addr));
#pragma unroll
                    for (int ht = 0; ht < 2; ht++) {
                        asm volatile(
                            "mma.sync.aligned.m16n8k16.row.col.f32.f16.f16.f32 "
                            "{%0,%1,%2,%3}, {%4,%5,%6,%7}, {%8,%9}, {%0,%1,%2,%3};"
                            : "+f"(c[et][ht][0]), "+f"(c[et][ht][1]),
                              "+f"(c[et][ht][2]), "+f"(c[et][ht][3])
                            : "r"(a0), "r"(a1), "r"(a2), "r"(a3),
                              "r"(bfr[ks][ht][0]), "r"(bfr[ks][ht][1]));
                    }
                }
            }

            // epilogue: 1 bfly shuffle -> 16B/lane coalesced STG.128
#pragma unroll
            for (int et = 0; et < 2; et++) {
#pragma unroll
                for (int hf = 0; hf < 2; hf++) {
                    float2 v0 = make_float2(c[et][0][hf * 2], c[et][0][hf * 2 + 1]);
                    float2 v1 = make_float2(c[et][1][hf * 2], c[et][1][hf * 2 + 1]);
                    float2 s  = (cq & 1) ? v0 : v1;   // what the partner needs
                    float2 r;
                    r.x = __shfl_xor_sync(0xffffffffu, s.x, 1);
                    r.y = __shfl_xor_sync(0xffffffffu, s.y, 1);
                    float4 w;
                    if (cq & 1) { w.x = r.x;  w.y = r.y;  w.z = v1.x; w.w = v1.y; }
                    else        { w.x = v0.x; w.y = v0.y; w.z = r.x;  w.w = r.y;  }
                    const int eg = eg_r[et][hf];
                    if (eg >= 0)
                        *(float4*)(out + (size_t)eg * HID + warp * 16 + chunk * 4) = w;
                }
            }
        };

        // ---- main loop: 2 groups per sync phase, 4-deep W ring ----
        for (int p = 0; p < ngr; p += 2) {
            const bool have1 = (p + 1 < ngr);
            const bool feed2 = (p + 2 < ngr);
            const bool feed3 = (p + 3 < ngr);

            if (feed2) ldg_group(p + 2);   // LDG early: hidden under MMA(p)
            do_group(p);
            if (feed2) sts_group(p + 2);   // into W[(p+2)&3], not read this phase

            if (have1) {
                if (feed3) ldg_group(p + 3);  // hidden under MMA(p+1)
                do_group(p + 1);
                if (feed3) sts_group(p + 3);
            }

            if (feed2) __syncthreads();  // phase boundary: W[p..p+1] free, W[p+2..p+3] published
        }
    } // k
}

extern "C" void kernel_launch(void* const* d_in, const int* in_sizes, int n_in,
                              void* d_out, int out_size) {
    // inputs (metadata order): h_v (unused), h_w, edge_features, edge_matrices
    const float* hw = (const float*)d_in[1];
    const float* ef = (const float*)d_in[2];
    const float* em = (const float*)d_in[3];
    float* out = (float*)d_out;
    const int E = in_sizes[1] / HID;
    const int NB = (E + EPB - 1) / EPB;

    // reset type counters: memset node (graph-capturable, cheaper than a kernel)
    void* cnt_addr = nullptr;
    cudaGetSymbolAddress(&cnt_addr, g_cnt);
    cudaMemsetAsync(cnt_addr, 0, KTYPES * sizeof(int));

    bin_kernel<<<NB, 256>>>(ef, E);

    cudaFuncSetAttribute(matmsg_main,
                         cudaFuncAttributeMaxDynamicSharedMemorySize, SMEM_BYTES);
    matmsg_main<<<(E + CH - 1) / CH, NTHREADS, SMEM_BYTES>>>(hw, em, out, E);
}

// round 16
// speedup vs baseline: 1.0168x; 1.0168x over previous
#include <cuda_runtime.h>
#include <cuda_fp16.h>
#include <cstdint>

#define HID       128
#define KTYPES    8
#define CH        768        // edges per main-kernel block
#define NTHREADS  256
#define GROUP     32         // edges per MMA group
#define MST       136        // smem stride (halves) for M tile  (128 + 8 pad)
#define WST       136        // smem stride (halves) for W tile
#define EPB       1024       // edges per bin block -> 313 blocks (full chip)
#define EMAX      327680

// dynamic smem (main kernel): M_s 34816 + W_s(2 buf) 17408
#define SMEM_M_OFF   0
#define SMEM_W_OFF   (128*MST*2)
#define SMEM_BYTES   (SMEM_W_OFF + 2*GROUP*WST*2)

// ---- global scratch (static device arrays are allowed) ----
__device__ int g_cnt[KTYPES];
__device__ int g_region[KTYPES][EMAX];   // per-type edge-id lists

__device__ __forceinline__ uint32_t smem_u32(const void* p) {
    return (uint32_t)__cvta_generic_to_shared(p);
}

__device__ __forceinline__ int decode_type(const float* __restrict__ ef, int e) {
    const float4* fp = (const float4*)(ef + (size_t)e * KTYPES);
    float4 f0 = fp[0], f1 = fp[1];
    int t = 0;
    if (f0.y > 0.5f) t = 1;
    if (f0.z > 0.5f) t = 2;
    if (f0.w > 0.5f) t = 3;
    if (f1.x > 0.5f) t = 4;
    if (f1.y > 0.5f) t = 5;
    if (f1.z > 0.5f) t = 6;
    if (f1.w > 0.5f) t = 7;
    return t;
}

// ---- K1: fused decode + block-aggregated append into per-type regions ----
extern "C" __global__ void __launch_bounds__(256)
bin_kernel(const float* __restrict__ ef, int E) {
    __shared__ int h[KTYPES];
    __shared__ int cur[KTYPES];
    const int tid  = threadIdx.x;
    const int base = blockIdx.x * EPB;
    if (tid < KTYPES) h[tid] = 0;
    __syncthreads();

    int ty[EPB / 256];
#pragma unroll
    for (int i = 0; i < EPB / 256; i++) {
        const int e = base + tid + i * 256;
        int t = 0;
        if (e < E) {
            t = decode_type(ef, e);
            atomicAdd(&h[t], 1);
        }
        ty[i] = t;
    }
    __syncthreads();
    if (tid < KTYPES) cur[tid] = atomicAdd(&g_cnt[tid], h[tid]);  // reserve slice
    __syncthreads();
#pragma unroll
    for (int i = 0; i < EPB / 256; i++) {
        const int e = base + tid + i * 256;
        if (e < E) {
            const int t = ty[i];
            const int p = atomicAdd(&cur[t], 1);
            g_region[t][p] = e;
        }
    }
}

__device__ __forceinline__ uint32_t f2h(float a, float b) {
    half2 h = __floats2half2_rn(a, b);
    return *reinterpret_cast<uint32_t*>(&h);
}

// ---- K2: main GEMM over virtually-sorted spans ----
extern "C" __global__ void __launch_bounds__(NTHREADS, 3)
matmsg_main(const float* __restrict__ hw,
            const float* __restrict__ em,
            float* __restrict__ out, int E)
{
    extern __shared__ char smem[];
    half* M_s = (half*)(smem + SMEM_M_OFF);   // [128][MST]
    half* W_s = (half*)(smem + SMEM_W_OFF);   // [2][32][WST]
    __shared__ int toff[KTYPES + 1];

    const int tid = threadIdx.x;
    if (tid == 0) {
        int acc = 0;
#pragma unroll
        for (int i = 0; i < KTYPES; i++) { toff[i] = acc; acc += g_cnt[i]; }
        toff[KTYPES] = acc;
    }
    __syncthreads();

    const int base = blockIdx.x * CH;
    const int hiB  = min(base + CH, E);

    const int warp = tid >> 5;
    const int lane = tid & 31;
    const int gr_r = tid >> 3;   // row this thread gathers (0..31)
    const int gr_q = tid & 7;    // 16-float chunk of the row
    const int cq    = lane & 3;
    const int chunk = ((cq & 1) << 1) | (cq >> 1);   // lane-quad -> 4-float chunk

    float4 pf[4];                // register prefetch buffer

    for (int k = 0; k < KTYPES; k++) {
        const int lo = max(base, toff[k]);
        const int hi = min(hiB, toff[k + 1]);
        if (lo >= hi) continue;
        const int nk = hi - lo;
        const int* __restrict__ ridx = &g_region[k][lo - toff[k]];

        __syncthreads();  // previous type's reads of M_s/W_s done

        // stage M_k (128x128 fp32) -> fp16 smem, STS.128 chunks
        {
            const float4* mp = (const float4*)(em + (size_t)k * HID * HID);
#pragma unroll
            for (int i = 0; i < 4; i++) {
                const int pi  = tid + i * NTHREADS;   // 16-half chunk id
                const int row = pi >> 3;
                const int chk = pi & 7;
                const float4* s = mp + row * 32 + chk * 4;
                float4 v0 = s[0], v1 = s[1], v2 = s[2], v3 = s[3];
                uint4 u0, u1;
                u0.x = f2h(v0.x, v0.y); u0.y = f2h(v0.z, v0.w);
                u0.z = f2h(v1.x, v1.y); u0.w = f2h(v1.z, v1.w);
                u1.x = f2h(v2.x, v2.y); u1.y = f2h(v2.z, v2.w);
                u1.z = f2h(v3.x, v3.y); u1.w = f2h(v3.z, v3.w);
                uint4* dst = (uint4*)&M_s[row * MST + chk * 16];
                dst[0] = u0; dst[1] = u1;
            }
        }

        const int ngr = (nk + GROUP - 1) / GROUP;

        // -- pipeline prologue --
        if (gr_r < nk) {
            const int eg = __ldg(&ridx[gr_r]);
            const float4* wp = (const float4*)(hw + (size_t)eg * HID) + gr_q * 4;
#pragma unroll
            for (int j = 0; j < 4; j++) pf[j] = wp[j];
        }
        {
            uint4* dst = (uint4*)&W_s[gr_r * WST + gr_q * 16];
            if (gr_r < nk) {
                uint4 u0, u1;
                u0.x = f2h(pf[0].x, pf[0].y); u0.y = f2h(pf[0].z, pf[0].w);
                u0.z = f2h(pf[1].x, pf[1].y); u0.w = f2h(pf[1].z, pf[1].w);
                u1.x = f2h(pf[2].x, pf[2].y); u1.y = f2h(pf[2].z, pf[2].w);
                u1.z = f2h(pf[3].x, pf[3].y); u1.w = f2h(pf[3].z, pf[3].w);
                dst[0] = u0; dst[1] = u1;
            } else {
                const uint4 z = make_uint4(0, 0, 0, 0);
                dst[0] = z; dst[1] = z;
            }
        }
        if (ngr > 1) {
            const int gr = GROUP + gr_r;
            if (gr < nk) {
                const int eg = __ldg(&ridx[gr]);
                const float4* wp = (const float4*)(hw + (size_t)eg * HID) + gr_q * 4;
#pragma unroll
                for (int j = 0; j < 4; j++) pf[j] = wp[j];
            }
        }
        __syncthreads();  // M_s + W_s buf0 ready

        // hoist M_k fragments (constant for the whole span)
        uint32_t bfr[8][2][2];
#pragma unroll
        for (int ks = 0; ks < 8; ks++) {
#pragma unroll
            for (int ht = 0; ht < 2; ht++) {
                const int nrow = warp * 16 + ht * 8 + (lane & 7);
                const int kcol = ks * 16 + ((lane >> 3) & 1) * 8;
                uint32_t addr = smem_u32(&M_s[nrow * MST + kcol]);
                asm volatile("ldmatrix.sync.aligned.m8n8.x2.shared.b16 {%0,%1}, [%2];"
                             : "=r"(bfr[ks][ht][0]), "=r"(bfr[ks][ht][1]) : "r"(addr));
            }
        }

        for (int g = 0; g < ngr; g++) {
            const half* Wb = &W_s[(g & 1) * GROUP * WST];

            // prefetch this group's epilogue edge ids (hidden under MMA)
            int eg_r[2][2];
#pragma unroll
            for (int et = 0; et < 2; et++)
#pragma unroll
                for (int hf = 0; hf < 2; hf++) {
                    const int gr = g * GROUP + et * 16 + hf * 8 + (lane >> 2);
                    eg_r[et][hf] = (gr < nk) ? __ldg(&ridx[gr]) : -1;
                }

            float c[2][2][4];
#pragma unroll
            for (int et = 0; et < 2; et++)
#pragma unroll
                for (int ht = 0; ht < 2; ht++)
#pragma unroll
                    for (int j = 0; j < 4; j++) c[et][ht][j] = 0.f;

#pragma unroll
            for (int ks = 0; ks < 8; ks++) {
#pragma unroll
                for (int et = 0; et < 2; et++) {
                    const int arow = et * 16 + (lane & 15);
                    const int acol = ks * 16 + (lane >> 4) * 8;
                    uint32_t addr = smem_u32(&Wb[arow * WST + acol]);
                    uint32_t a0, a1, a2, a3;
                    asm volatile("ldmatrix.sync.aligned.m8n8.x4.shared.b16 {%0,%1,%2,%3}, [%4];"
                                 : "=r"(a0), "=r"(a1), "=r"(a2), "=r"(a3) : "r"(addr));
#pragma unroll
                    for (int ht = 0; ht < 2; ht++) {
                        asm volatile(
                            "mma.sync.aligned.m16n8k16.row.col.f32.f16.f16.f32 "
                            "{%0,%1,%2,%3}, {%4,%5,%6,%7}, {%8,%9}, {%0,%1,%2,%3};"
                            : "+f"(c[et][ht][0]), "+f"(c[et][ht][1]),
                              "+f"(c[et][ht][2]), "+f"(c[et][ht][3])
                            : "r"(a0), "r"(a1), "r"(a2), "r"(a3),
                              "r"(bfr[ks][ht][0]), "r"(bfr[ks][ht][1]));
                    }
                }
            }

            // ---- feed pipeline FIRST: STS group g+1 (in regs), LDG group g+2 ----
            if (g + 1 < ngr) {
                const int gr1 = (g + 1) * GROUP + gr_r;
                uint4* dst = (uint4*)&W_s[((g + 1) & 1) * GROUP * WST + gr_r * WST + gr_q * 16];
                if (gr1 < nk) {
                    uint4 u0, u1;
                    u0.x = f2h(pf[0].x, pf[0].y); u0.y = f2h(pf[0].z, pf[0].w);
                    u0.z = f2h(pf[1].x, pf[1].y); u0.w = f2h(pf[1].z, pf[1].w);
                    u1.x = f2h(pf[2].x, pf[2].y); u1.y = f2h(pf[2].z, pf[2].w);
                    u1.z = f2h(pf[3].x, pf[3].y); u1.w = f2h(pf[3].z, pf[3].w);
                    dst[0] = u0; dst[1] = u1;
                } else {
                    const uint4 z = make_uint4(0, 0, 0, 0);
                    dst[0] = z; dst[1] = z;
                }
                if (g + 2 < ngr) {
                    const int gr2 = (g + 2) * GROUP + gr_r;
                    if (gr2 < nk) {
                        const int eg = __ldg(&ridx[gr2]);
                        const float4* wp = (const float4*)(hw + (size_t)eg * HID) + gr_q * 4;
#pragma unroll
                        for (int j = 0; j < 4; j++) pf[j] = wp[j];
                    }
                }
            }

            // ---- epilogue: 1 bfly shuffle -> 16B/lane coalesced STG.128 ----
            // (fire-and-forget; fills the window before the barrier)
#pragma unroll
            for (int et = 0; et < 2; et++) {
#pragma unroll
                for (int hf = 0; hf < 2; hf++) {
                    float2 v0 = make_float2(c[et][0][hf * 2], c[et][0][hf * 2 + 1]);
                    float2 v1 = make_float2(c[et][1][hf * 2], c[et][1][hf * 2 + 1]);
                    float2 s  = (cq & 1) ? v0 : v1;   // what the partner needs
                    float2 r;
                    r.x = __shfl_xor_sync(0xffffffffu, s.x, 1);
                    r.y = __shfl_xor_sync(0xffffffffu, s.y, 1);
                    float4 w;
                    if (cq & 1) { w.x = r.x;  w.y = r.y;  w.z = v1.x; w.w = v1.y; }
                    else        { w.x = v0.x; w.y = v0.y; w.z = r.x;  w.w = r.y;  }
                    const int eg = eg_r[et][hf];
                    if (eg >= 0)
                        *(float4*)(out + (size_t)eg * HID + warp * 16 + chunk * 4) = w;
                }
            }

            if (g + 1 < ngr)
                __syncthreads();  // STS(g+1) visible; reads of buf(g) done
        } // groups
    } // k
}

extern "C" void kernel_launch(void* const* d_in, const int* in_sizes, int n_in,
                              void* d_out, int out_size) {
    // inputs (metadata order): h_v (unused), h_w, edge_features, edge_matrices
    const float* hw = (const float*)d_in[1];
    const float* ef = (const float*)d_in[2];
    const float* em = (const float*)d_in[3];
    float* out = (float*)d_out;
    const int E = in_sizes[1] / HID;
    const int NB = (E + EPB - 1) / EPB;

    // reset type counters: memset node (graph-capturable, cheaper than a kernel)
    void* cnt_addr = nullptr;
    cudaGetSymbolAddress(&cnt_addr, g_cnt);
    cudaMemsetAsync(cnt_addr, 0, KTYPES * sizeof(int));

    bin_kernel<<<NB, 256>>>(ef, E);

    cudaFuncSetAttribute(matmsg_main,
                         cudaFuncAttributeMaxDynamicSharedMemorySize, SMEM_BYTES);
    matmsg_main<<<(E + CH - 1) / CH, NTHREADS, SMEM_BYTES>>>(hw, em, out, E);
}

// round 17
// speedup vs baseline: 1.1399x; 1.1210x over previous
#include <cuda_runtime.h>
#include <cuda_fp16.h>
#include <cstdint>

#define HID       128
#define KTYPES    8
#define CH        736        // edges per block -> grid 435 <= 444 slots (single wave)
#define NTHREADS  256
#define GROUP     32         // edges per MMA group
#define MST       136        // smem stride (halves) for M tile  (128 + 8 pad)
#define WST       136        // smem stride (halves) for W tile
#define EPB       1024       // edges per bin block -> 313 blocks (full chip)
#define EMAX      327680

// dynamic smem (main kernel): M_s 34816 + W_s(2 buf) 17408
#define SMEM_M_OFF   0
#define SMEM_W_OFF   (128*MST*2)
#define SMEM_BYTES   (SMEM_W_OFF + 2*GROUP*WST*2)

// ---- global scratch (static device arrays are allowed) ----
__device__ int g_cnt[KTYPES];
__device__ int g_region[KTYPES][EMAX];   // per-type edge-id lists

__device__ __forceinline__ uint32_t smem_u32(const void* p) {
    return (uint32_t)__cvta_generic_to_shared(p);
}

__device__ __forceinline__ int decode_type(const float* __restrict__ ef, int e) {
    const float4* fp = (const float4*)(ef + (size_t)e * KTYPES);
    float4 f0 = fp[0], f1 = fp[1];
    int t = 0;
    if (f0.y > 0.5f) t = 1;
    if (f0.z > 0.5f) t = 2;
    if (f0.w > 0.5f) t = 3;
    if (f1.x > 0.5f) t = 4;
    if (f1.y > 0.5f) t = 5;
    if (f1.z > 0.5f) t = 6;
    if (f1.w > 0.5f) t = 7;
    return t;
}

// ---- K1: fused decode + block-aggregated append into per-type regions ----
extern "C" __global__ void __launch_bounds__(256)
bin_kernel(const float* __restrict__ ef, int E) {
    __shared__ int h[KTYPES];
    __shared__ int cur[KTYPES];
    const int tid  = threadIdx.x;
    const int base = blockIdx.x * EPB;
    if (tid < KTYPES) h[tid] = 0;
    __syncthreads();

    int ty[EPB / 256];
#pragma unroll
    for (int i = 0; i < EPB / 256; i++) {
        const int e = base + tid + i * 256;
        int t = 0;
        if (e < E) {
            t = decode_type(ef, e);
            atomicAdd(&h[t], 1);
        }
        ty[i] = t;
    }
    __syncthreads();
    if (tid < KTYPES) cur[tid] = atomicAdd(&g_cnt[tid], h[tid]);  // reserve slice
    __syncthreads();
#pragma unroll
    for (int i = 0; i < EPB / 256; i++) {
        const int e = base + tid + i * 256;
        if (e < E) {
            const int t = ty[i];
            const int p = atomicAdd(&cur[t], 1);
            g_region[t][p] = e;
        }
    }
}

__device__ __forceinline__ uint32_t f2h(float a, float b) {
    half2 h = __floats2half2_rn(a, b);
    return *reinterpret_cast<uint32_t*>(&h);
}

// ---- K2: main GEMM over virtually-sorted spans ----
extern "C" __global__ void __launch_bounds__(NTHREADS, 3)
matmsg_main(const float* __restrict__ hw,
            const float* __restrict__ em,
            float* __restrict__ out, int E)
{
    extern __shared__ char smem[];
    half* M_s = (half*)(smem + SMEM_M_OFF);   // [128][MST]
    half* W_s = (half*)(smem + SMEM_W_OFF);   // [2][32][WST]
    __shared__ int toff[KTYPES + 1];

    const int tid = threadIdx.x;
    if (tid == 0) {
        int acc = 0;
#pragma unroll
        for (int i = 0; i < KTYPES; i++) { toff[i] = acc; acc += g_cnt[i]; }
        toff[KTYPES] = acc;
    }
    __syncthreads();

    const int base = blockIdx.x * CH;
    const int hiB  = min(base + CH, E);

    const int warp = tid >> 5;
    const int lane = tid & 31;
    const int gr_r = tid >> 3;   // row this thread gathers (0..31)
    const int gr_q = tid & 7;    // 16-float chunk of the row
    const int cq    = lane & 3;
    const int chunk = ((cq & 1) << 1) | (cq >> 1);   // lane-quad -> 4-float chunk

    float4 pf[4];                // register prefetch buffer

    for (int k = 0; k < KTYPES; k++) {
        const int lo = max(base, toff[k]);
        const int hi = min(hiB, toff[k + 1]);
        if (lo >= hi) continue;
        const int nk = hi - lo;
        const int* __restrict__ ridx = &g_region[k][lo - toff[k]];

        __syncthreads();  // previous type's reads of M_s/W_s done

        // stage M_k (128x128 fp32) -> fp16 smem, STS.128 chunks
        {
            const float4* mp = (const float4*)(em + (size_t)k * HID * HID);
#pragma unroll
            for (int i = 0; i < 4; i++) {
                const int pi  = tid + i * NTHREADS;   // 16-half chunk id
                const int row = pi >> 3;
                const int chk = pi & 7;
                const float4* s = mp + row * 32 + chk * 4;
                float4 v0 = s[0], v1 = s[1], v2 = s[2], v3 = s[3];
                uint4 u0, u1;
                u0.x = f2h(v0.x, v0.y); u0.y = f2h(v0.z, v0.w);
                u0.z = f2h(v1.x, v1.y); u0.w = f2h(v1.z, v1.w);
                u1.x = f2h(v2.x, v2.y); u1.y = f2h(v2.z, v2.w);
                u1.z = f2h(v3.x, v3.y); u1.w = f2h(v3.z, v3.w);
                uint4* dst = (uint4*)&M_s[row * MST + chk * 16];
                dst[0] = u0; dst[1] = u1;
            }
        }

        const int ngr = (nk + GROUP - 1) / GROUP;

        // -- pipeline prologue --
        if (gr_r < nk) {
            const int eg = __ldg(&ridx[gr_r]);
            const float4* wp = (const float4*)(hw + (size_t)eg * HID) + gr_q * 4;
#pragma unroll
            for (int j = 0; j < 4; j++) pf[j] = wp[j];
        }
        {
            uint4* dst = (uint4*)&W_s[gr_r * WST + gr_q * 16];
            if (gr_r < nk) {
                uint4 u0, u1;
                u0.x = f2h(pf[0].x, pf[0].y); u0.y = f2h(pf[0].z, pf[0].w);
                u0.z = f2h(pf[1].x, pf[1].y); u0.w = f2h(pf[1].z, pf[1].w);
                u1.x = f2h(pf[2].x, pf[2].y); u1.y = f2h(pf[2].z, pf[2].w);
                u1.z = f2h(pf[3].x, pf[3].y); u1.w = f2h(pf[3].z, pf[3].w);
                dst[0] = u0; dst[1] = u1;
            } else {
                const uint4 z = make_uint4(0, 0, 0, 0);
                dst[0] = z; dst[1] = z;
            }
        }
        if (ngr > 1) {
            const int gr = GROUP + gr_r;
            if (gr < nk) {
                const int eg = __ldg(&ridx[gr]);
                const float4* wp = (const float4*)(hw + (size_t)eg * HID) + gr_q * 4;
#pragma unroll
                for (int j = 0; j < 4; j++) pf[j] = wp[j];
            }
        }
        __syncthreads();  // M_s + W_s buf0 ready

        // hoist M_k fragments (constant for the whole span)
        uint32_t bfr[8][2][2];
#pragma unroll
        for (int ks = 0; ks < 8; ks++) {
#pragma unroll
            for (int ht = 0; ht < 2; ht++) {
                const int nrow = warp * 16 + ht * 8 + (lane & 7);
                const int kcol = ks * 16 + ((lane >> 3) & 1) * 8;
                uint32_t addr = smem_u32(&M_s[nrow * MST + kcol]);
                asm volatile("ldmatrix.sync.aligned.m8n8.x2.shared.b16 {%0,%1}, [%2];"
                             : "=r"(bfr[ks][ht][0]), "=r"(bfr[ks][ht][1]) : "r"(addr));
            }
        }

        for (int g = 0; g < ngr; g++) {
            const half* Wb = &W_s[(g & 1) * GROUP * WST];

            // prefetch this group's epilogue edge ids (hidden under MMA)
            int eg_r[2][2];
#pragma unroll
            for (int et = 0; et < 2; et++)
#pragma unroll
                for (int hf = 0; hf < 2; hf++) {
                    const int gr = g * GROUP + et * 16 + hf * 8 + (lane >> 2);
                    eg_r[et][hf] = (gr < nk) ? __ldg(&ridx[gr]) : -1;
                }

            float c[2][2][4];
#pragma unroll
            for (int et = 0; et < 2; et++)
#pragma unroll
                for (int ht = 0; ht < 2; ht++)
#pragma unroll
                    for (int j = 0; j < 4; j++) c[et][ht][j] = 0.f;

#pragma unroll
            for (int ks = 0; ks < 8; ks++) {
#pragma unroll
                for (int et = 0; et < 2; et++) {
                    const int arow = et * 16 + (lane & 15);
                    const int acol = ks * 16 + (lane >> 4) * 8;
                    uint32_t addr = smem_u32(&Wb[arow * WST + acol]);
                    uint32_t a0, a1, a2, a3;
                    asm volatile("ldmatrix.sync.aligned.m8n8.x4.shared.b16 {%0,%1,%2,%3}, [%4];"
                                 : "=r"(a0), "=r"(a1), "=r"(a2), "=r"(a3) : "r"(addr));
#pragma unroll
                    for (int ht = 0; ht < 2; ht++) {
                        asm volatile(
                            "mma.sync.aligned.m16n8k16.row.col.f32.f16.f16.f32 "
                            "{%0,%1,%2,%3}, {%4,%5,%6,%7}, {%8,%9}, {%0,%1,%2,%3};"
                            : "+f"(c[et][ht][0]), "+f"(c[et][ht][1]),
                              "+f"(c[et][ht][2]), "+f"(c[et][ht][3])
                            : "r"(a0), "r"(a1), "r"(a2), "r"(a3),
                              "r"(bfr[ks][ht][0]), "r"(bfr[ks][ht][1]));
                    }
                }
            }

            // ---- epilogue: 1 bfly shuffle -> 16B/lane coalesced STG.128 ----
#pragma unroll
            for (int et = 0; et < 2; et++) {
#pragma unroll
                for (int hf = 0; hf < 2; hf++) {
                    float2 v0 = make_float2(c[et][0][hf * 2], c[et][0][hf * 2 + 1]);
                    float2 v1 = make_float2(c[et][1][hf * 2], c[et][1][hf * 2 + 1]);
                    float2 s  = (cq & 1) ? v0 : v1;   // what the partner needs
                    float2 r;
                    r.x = __shfl_xor_sync(0xffffffffu, s.x, 1);
                    r.y = __shfl_xor_sync(0xffffffffu, s.y, 1);
                    float4 w;
                    if (cq & 1) { w.x = r.x;  w.y = r.y;  w.z = v1.x; w.w = v1.y; }
                    else        { w.x = v0.x; w.y = v0.y; w.z = r.x;  w.w = r.y;  }
                    const int eg = eg_r[et][hf];
                    if (eg >= 0)
                        *(float4*)(out + (size_t)eg * HID + warp * 16 + chunk * 4) = w;
                }
            }

            // ---- feed pipeline: STS group g+1 (in regs), LDG group g+2 ----
            if (g + 1 < ngr) {
                const int gr1 = (g + 1) * GROUP + gr_r;
                uint4* dst = (uint4*)&W_s[((g + 1) & 1) * GROUP * WST + gr_r * WST + gr_q * 16];
                if (gr1 < nk) {
                    uint4 u0, u1;
                    u0.x = f2h(pf[0].x, pf[0].y); u0.y = f2h(pf[0].z, pf[0].w);
                    u0.z = f2h(pf[1].x, pf[1].y); u0.w = f2h(pf[1].z, pf[1].w);
                    u1.x = f2h(pf[2].x, pf[2].y); u1.y = f2h(pf[2].z, pf[2].w);
                    u1.z = f2h(pf[3].x, pf[3].y); u1.w = f2h(pf[3].z, pf[3].w);
                    dst[0] = u0; dst[1] = u1;
                } else {
                    const uint4 z = make_uint4(0, 0, 0, 0);
                    dst[0] = z; dst[1] = z;
                }
                if (g + 2 < ngr) {
                    const int gr2 = (g + 2) * GROUP + gr_r;
                    if (gr2 < nk) {
                        const int eg = __ldg(&ridx[gr2]);
                        const float4* wp = (const float4*)(hw + (size_t)eg * HID) + gr_q * 4;
#pragma unroll
                        for (int j = 0; j < 4; j++) pf[j] = wp[j];
                    }
                }
                __syncthreads();  // STS(g+1) visible; reads of buf(g) done
            }
        } // groups
    } // k
}

extern "C" void kernel_launch(void* const* d_in, const int* in_sizes, int n_in,
                              void* d_out, int out_size) {
    // inputs (metadata order): h_v (unused), h_w, edge_features, edge_matrices
    const float* hw = (const float*)d_in[1];
    const float* ef = (const float*)d_in[2];
    const float* em = (const float*)d_in[3];
    float* out = (float*)d_out;
    const int E = in_sizes[1] / HID;
    const int NB = (E + EPB - 1) / EPB;

    // reset type counters: memset node (graph-capturable, cheaper than a kernel)
    void* cnt_addr = nullptr;
    cudaGetSymbolAddress(&cnt_addr, g_cnt);
    cudaMemsetAsync(cnt_addr, 0, KTYPES * sizeof(int));

    bin_kernel<<<NB, 256>>>(ef, E);

    cudaFuncSetAttribute(matmsg_main,
                         cudaFuncAttributeMaxDynamicSharedMemorySize, SMEM_BYTES);
    matmsg_main<<<(E + CH - 1) / CH, NTHREADS, SMEM_BYTES>>>(hw, em, out, E);
}